// round 4
// baseline (speedup 1.0000x reference)
#include <cuda_runtime.h>
#include <cuda_bf16.h>

// LIF spiking scan:  x[B,S,H] -> spikes[B,S,H]
//   mem = decay*mem + x_t ; ref = max(ref-1,0)
//   spk = (ref==0 && mem>thr) ; mem *= (1-spk) ; ref += 5*spk
//
// Parallel over B*H = 32768 neurons (sequential over S=2048).
// HBM-bound: 512 MB traffic -> ~75-90 us floor. Only ~221 threads/SM exist,
// so we need ~28 outstanding 4B loads per thread: register double-buffered
// time chunks of U=32, ping-pong unrolled outer loop (no buffer-copy MOVs).
// All indexing in 32-bit: total elements = 2^26, byte offsets < 2^28.

#define LIF_B 8
#define LIF_S 2048
#define LIF_H 4096

static constexpr int U = 32;                 // timesteps per chunk
static constexpr int NCHUNK = LIF_S / U;     // 64
static constexpr float REFRACTORY = 5.0f;

__global__ __launch_bounds__(128, 1)
void lif_scan_kernel(const float* __restrict__ x,
                     const float* __restrict__ thr_p,
                     const float* __restrict__ dec_p,
                     float* __restrict__ out)
{
    const int n = blockIdx.x * blockDim.x + threadIdx.x;   // 0..32767, exact cover
    const float thr   = __ldg(thr_p);
    const float decay = __ldg(dec_p);

    const int b = n >> 12;            // n / H
    const int h = n & (LIF_H - 1);    // n % H
    const int base = b * (LIF_S * LIF_H) + h;   // < 2^26, fits int
    const float* __restrict__ xp = x + base;
    float* __restrict__ op = out + base;

    float mem = 0.0f;
    float ref = 0.0f;

    float bufA[U];
    float bufB[U];

    // Preload chunk 0 (32 independent LDGs, front-batched)
#pragma unroll
    for (int i = 0; i < U; ++i)
        bufA[i] = __ldg(&xp[i * LIF_H]);

    for (int c = 0; c < NCHUNK; c += 2) {
        const float* __restrict__ xc = xp + c * (U * LIF_H);
        float* __restrict__ oc       = op + c * (U * LIF_H);

        // ---- prefetch chunk c+1 (always exists: c <= NCHUNK-2) ----
#pragma unroll
        for (int i = 0; i < U; ++i)
            bufB[i] = __ldg(&xc[(U + i) * LIF_H]);

        // ---- compute chunk c from bufA ----
#pragma unroll
        for (int i = 0; i < U; ++i) {
            mem = fmaf(decay, mem, bufA[i]);
            ref = fmaxf(ref - 1.0f, 0.0f);
            const bool sp = (ref == 0.0f) && (mem > thr);
            const float s = sp ? 1.0f : 0.0f;
            mem = sp ? 0.0f : mem;
            ref = fmaf(s, REFRACTORY, ref);
            oc[i * LIF_H] = s;
        }

        // ---- prefetch chunk c+2 (guarded; predictable branch) ----
        if (c + 2 < NCHUNK) {
#pragma unroll
            for (int i = 0; i < U; ++i)
                bufA[i] = __ldg(&xc[(2 * U + i) * LIF_H]);
        }

        // ---- compute chunk c+1 from bufB ----
#pragma unroll
        for (int i = 0; i < U; ++i) {
            mem = fmaf(decay, mem, bufB[i]);
            ref = fmaxf(ref - 1.0f, 0.0f);
            const bool sp = (ref == 0.0f) && (mem > thr);
            const float s = sp ? 1.0f : 0.0f;
            mem = sp ? 0.0f : mem;
            ref = fmaf(s, REFRACTORY, ref);
            oc[(U + i) * LIF_H] = s;
        }
    }
}

extern "C" void kernel_launch(void* const* d_in, const int* in_sizes, int n_in,
                              void* d_out, int out_size)
{
    // metadata order: x [B,S,H] f32, membrane_threshold f32 scalar, decay_rate f32 scalar
    const float* x     = (const float*)d_in[0];
    const float* thr_p = (const float*)d_in[1];
    const float* dec_p = (const float*)d_in[2];
    float* out = (float*)d_out;

    const int n_neurons = LIF_B * LIF_H;          // 32768
    const int threads = 128;
    const int blocks = n_neurons / threads;        // 256, exact single wave

    lif_scan_kernel<<<blocks, threads>>>(x, thr_p, dec_p, out);
}

// round 6
// speedup vs baseline: 1.4330x; 1.4330x over previous
#include <cuda_runtime.h>
#include <cuda_bf16.h>
#include <cstdint>

// LIF spiking scan:  x[B,S,H] -> spikes[B,S,H]   (B=8, S=2048, H=4096, fp32)
//   mem = decay*mem + x_t ; ref = max(ref-1,0)
//   spk = (ref==0 && mem>thr) ; mem *= (1-spk) ; ref += 5*spk
//
// Strictly sequential over S, parallel over B*H = 32768 neurons (fixed thread
// count -> occupancy is structural). HBM-bound: 512 MB traffic, floor ~75 us.
// R4 (register double-buffer) hit 143.8us @ 44% DRAM: in-flight bytes had no
// headroom and the burst (32 LDG -> serial compute -> stall) left pipeline
// bubbles. R5/R6: cp.async multistage SMEM pipeline. Each block owns 128
// neurons; a chunk = 16 timesteps x 512B contiguous rows, copied
// cooperatively with 4x 16B cp.async.cg per thread. 6 stages (48KB static
// smem), 4 chunks in flight -> ~8MB chip-wide in-flight (2x latency-BW
// product), smooth producer stream decoupled from the serial compute chain.

#define LIF_B 8
#define LIF_S 2048
#define LIF_H 4096

static constexpr int U = 16;               // timesteps per stage
static constexpr int STAGES = 6;           // 6*16*128*4B = 48KB static smem
static constexpr int NCHUNK = LIF_S / U;   // 128
static constexpr float REFRACTORY = 5.0f;

__global__ __launch_bounds__(128, 1)
void lif_scan_pipe(const float* __restrict__ x,
                   const float* __restrict__ thr_p,
                   const float* __restrict__ dec_p,
                   float* __restrict__ out)
{
    __shared__ float smem[STAGES][U][128];

    const int tid = threadIdx.x;
    const int n0  = blockIdx.x * 128;        // first neuron of this block
    const int b     = n0 >> 12;              // n0 / H  (blocks never straddle b)
    const int hbase = n0 & (LIF_H - 1);      // n0 % H

    const float thr   = __ldg(thr_p);
    const float decay = __ldg(dec_p);

    const float* __restrict__ xbase = x   + b * (LIF_S * LIF_H) + hbase;
    float* __restrict__       obase = out + b * (LIF_S * LIF_H) + hbase + tid;

    // Cooperative-copy role: 16 rows x 32 float4 columns, 128 threads.
    // thread -> (row = (tid>>5) + 4*j, col = tid&31), j = 0..3
    const int crow = tid >> 5;   // 0..3
    const int ccol = tid & 31;   // 0..31

    auto issue_chunk = [&](int c) {
        const int s = c % STAGES;
        const float* src = xbase + (c * U) * LIF_H + ccol * 4;
        #pragma unroll
        for (int j = 0; j < 4; ++j) {
            const int row = crow + j * 4;
            unsigned dst = (unsigned)__cvta_generic_to_shared(&smem[s][row][ccol * 4]);
            const float* g = src + row * LIF_H;
            asm volatile("cp.async.cg.shared.global [%0], [%1], 16;\n"
                         :: "r"(dst), "l"(g));
        }
    };

    // Prologue: fill STAGES-2 stages (chunks 0..STAGES-3), one group each.
    #pragma unroll
    for (int c = 0; c < STAGES - 2; ++c) {
        issue_chunk(c);
        asm volatile("cp.async.commit_group;\n" ::: "memory");
    }

    float mem = 0.0f;
    float ref = 0.0f;

    for (int c = 0; c < NCHUNK; ++c) {
        // Issue chunk c+STAGES-2 (writes stage read at iter c-2; the barrier
        // at iter c-1 orders all threads' reads before this write).
        if (c + STAGES - 2 < NCHUNK)
            issue_chunk(c + STAGES - 2);
        // Always commit (empty groups in the tail keep the count aligned so
        // wait_group<STAGES-2> still guarantees chunk c's group is complete).
        asm volatile("cp.async.commit_group;\n" ::: "memory");
        asm volatile("cp.async.wait_group %0;\n" :: "n"(STAGES - 2) : "memory");
        __syncthreads();   // chunk c fully resident for all threads

        const int s = c % STAGES;

        // Batch the 16 LDS (conflict-free: lanes hit consecutive banks).
        float v[U];
        #pragma unroll
        for (int i = 0; i < U; ++i)
            v[i] = smem[s][i][tid];

        float* __restrict__ o = obase + (c * U) * LIF_H;
        #pragma unroll
        for (int i = 0; i < U; ++i) {
            mem = fmaf(decay, mem, v[i]);
            ref = fmaxf(ref - 1.0f, 0.0f);
            const bool sp = (ref == 0.0f) && (mem > thr);
            const float spk = sp ? 1.0f : 0.0f;
            mem = sp ? 0.0f : mem;
            ref = fmaf(spk, REFRACTORY, ref);
            o[i * LIF_H] = spk;
        }
    }
}

extern "C" void kernel_launch(void* const* d_in, const int* in_sizes, int n_in,
                              void* d_out, int out_size)
{
    // metadata order: x [B,S,H] f32, membrane_threshold f32, decay_rate f32
    const float* x     = (const float*)d_in[0];
    const float* thr_p = (const float*)d_in[1];
    const float* dec_p = (const float*)d_in[2];
    float* out = (float*)d_out;

    const int blocks = (LIF_B * LIF_H) / 128;   // 256 blocks, exact cover

    lif_scan_pipe<<<blocks, 128>>>(x, thr_p, dec_p, out);
}